// round 13
// baseline (speedup 1.0000x reference)
#include <cuda_runtime.h>
#include <math.h>

#define BATCH 256
#define DI    5120
#define RNK   160
#define NS    16
#define RX    192            // 160 (delta) + 16 (B) + 16 (C)

#define KS1   40             // split-K factor for GEMM1
#define KCH   (DI / KS1)     // 128
#define BT1   8              // batch tile GEMM1
#define WCH   16             // w prefetch chunk GEMM1

#define BT2   8              // batch tile fused kernel
#define DCH2  256            // d's (= threads) per fused block
#define RCH   8              // Wdt prefetch chunk

#define LOG2E 1.4426950408889634f

// ---- scratch (no dynamic allocation allowed) ----
__device__ float g_part[KS1 * BATCH * RX];   // GEMM1 split-K partials
__device__ float g_xd[BATCH * RX];           // [xd | Bp | C]
__device__ float g_negA[DI * NS];            // [d][n]: -exp(A_log)*log2e

__device__ __forceinline__ float ex2(float v) {
    float r;
    asm("ex2.approx.ftz.f32 %0, %1;" : "=f"(r) : "f"(v));
    return r;
}

// ---------------------------------------------------------------- prep
__global__ void k_prep(const float* __restrict__ A_log) {
    int i = blockIdx.x * blockDim.x + threadIdx.x;
    if (i < DI * NS) g_negA[i] = -expf(A_log[i]) * LOG2E;
}

// ---------------------------------------------------------------- GEMM1 core
template <int WSTR>
__device__ __forceinline__ void gemm1_core(const float* __restrict__ w0,
                                           const float* __restrict__ xs,
                                           float* __restrict__ acc) {
    float wbuf[2][WCH];
    const float* wp = w0;
#pragma unroll
    for (int j = 0; j < WCH; j++) wbuf[0][j] = wp[j * WSTR];

#pragma unroll
    for (int c = 0; c < KCH / WCH; c++) {
        const int cur = c & 1;                 // compile-time
        if (c + 1 < KCH / WCH) {
            const float* wn = wp + WCH * WSTR;
#pragma unroll
            for (int j = 0; j < WCH; j++) wbuf[cur ^ 1][j] = wn[j * WSTR];
        }
#pragma unroll
        for (int j = 0; j < WCH; j++) {
            float w = wbuf[cur][j];
            const float4* xv4 = reinterpret_cast<const float4*>(xs + (c * WCH + j) * BT1);
#pragma unroll
            for (int q = 0; q < BT1 / 4; q++) {
                float4 xv = xv4[q];
                acc[4*q+0] += xv.x * w;
                acc[4*q+1] += xv.y * w;
                acc[4*q+2] += xv.z * w;
                acc[4*q+3] += xv.w * w;
            }
        }
        wp += WCH * WSTR;
    }
}

// ---------------------------------------------------------------- GEMM1
__global__ void __launch_bounds__(RX)
k_gemm1(const float* __restrict__ x,
        const float* __restrict__ Wd,
        const float* __restrict__ WB,
        const float* __restrict__ WC) {
    __shared__ float xs[KCH * BT1];         // [kk][bb]  4 KB
    const int r  = threadIdx.x;             // 0..191
    const int b0 = blockIdx.x * BT1;
    const int k0 = blockIdx.y * KCH;

    for (int i = r; i < KCH * BT1; i += RX) {
        int bb = i / KCH, kk = i - bb * KCH;
        xs[kk * BT1 + bb] = x[(b0 + bb) * DI + k0 + kk];
    }

    float acc[BT1];
#pragma unroll
    for (int i = 0; i < BT1; i++) acc[i] = 0.f;

    __syncthreads();

    if (r < 160) {
        gemm1_core<160>(Wd + r + k0 * 160, xs, acc);
    } else {
        const float* wb = (r < 176) ? (WB + (r - 160) + k0 * 16)
                                    : (WC + (r - 176) + k0 * 16);
        gemm1_core<16>(wb, xs, acc);
    }

    float* out = g_part + (blockIdx.y * BATCH + b0) * RX + r;
#pragma unroll
    for (int bb = 0; bb < BT1; bb++) out[bb * RX] = acc[bb];
}

// ---------------------------------------------------------------- reduce
__global__ void k_reduce() {
    int i = blockIdx.x * blockDim.x + threadIdx.x;    // float4 index
    if (i >= BATCH * RX / 4) return;
    const float4* p = reinterpret_cast<const float4*>(g_part) + i;
    float4 s = make_float4(0.f, 0.f, 0.f, 0.f);
#pragma unroll
    for (int ks = 0; ks < KS1; ks++) {
        float4 v = p[ks * (BATCH * RX / 4)];
        s.x += v.x; s.y += v.y; s.z += v.z; s.w += v.w;
    }
    reinterpret_cast<float4*>(g_xd)[i] = s;
}

// ---------------------------------------------------------------- fused GEMM2 + softplus + SSM
// grid (BATCH/BT2, DI/DCH2): consecutive CTAs share the same Wdt slice (L2 reuse).
// Phase 1: 1 d per thread, 8 batches, barrier-free register-prefetched Wdt.
// Phase 2: 4 lanes per d; 2 groups of 4 batches; butterfly-transpose reduction
//          (2 shfls per 4 results, lane q owns batch g*4+q, unpredicated store).
__global__ void __launch_bounds__(DCH2, 5)
k_fused2(const float* __restrict__ x,
         const float* __restrict__ h,
         const float* __restrict__ Wdt,
         const float* __restrict__ b_dt,
         const float* __restrict__ Dv,
         float* __restrict__ y) {
    __shared__ float xds[RNK * BT2];        // [r][bb]   5 KB
    __shared__ float sdt[BT2 * DCH2];       // [bb][d]   8 KB
    __shared__ float sBC[BT2 * 2 * NS];     // per batch: B[16] | C[16]  2 KB
    __shared__ float sbc[BT2];              // dot(B,C) per batch
    const int tid = threadIdx.x;            // 0..255
    const int b0  = blockIdx.x * BT2;
    const int d   = blockIdx.y * DCH2 + tid;

    for (int i = tid; i < RNK * BT2; i += DCH2) {
        int r = i >> 3, bb = i & 7;
        xds[i] = g_xd[(b0 + bb) * RX + r];
    }
    for (int i = tid; i < BT2 * 2 * NS; i += DCH2) {
        int bb = i >> 5, j = i & 31;
        sBC[i] = g_xd[(b0 + bb) * RX + 160 + j];
    }
    __syncthreads();

    if (tid < BT2) {
        float s = 0.f;
#pragma unroll
        for (int n = 0; n < NS; n++) s += sBC[tid * 32 + n] * sBC[tid * 32 + NS + n];
        sbc[tid] = s;
    }

    // ---- Phase 1: GEMM2 (register double-buffered W, fully unrolled)
    float acc[BT2];
#pragma unroll
    for (int i = 0; i < BT2; i++) acc[i] = 0.f;

    const float* wp = Wdt + d;
    float wbuf[2][RCH];
#pragma unroll
    for (int j = 0; j < RCH; j++) wbuf[0][j] = wp[j * DI];

#pragma unroll
    for (int c = 0; c < RNK / RCH; c++) {   // 20 chunks
        const int cur = c & 1;               // compile-time
        if (c + 1 < RNK / RCH) {
            const float* wn = wp + RCH * DI;
#pragma unroll
            for (int j = 0; j < RCH; j++) wbuf[cur ^ 1][j] = wn[j * DI];
        }
        const int rbase = c * RCH;
#pragma unroll
        for (int j = 0; j < RCH; j++) {
            float w = wbuf[cur][j];
            const float4* xp = reinterpret_cast<const float4*>(xds + (rbase + j) * BT2);
            float4 xa = xp[0], xb = xp[1];
            acc[0] += xa.x * w;  acc[1] += xa.y * w;
            acc[2] += xa.z * w;  acc[3] += xa.w * w;
            acc[4] += xb.x * w;  acc[5] += xb.y * w;
            acc[6] += xb.z * w;  acc[7] += xb.w * w;
        }
        wp += RCH * DI;
    }

    {
        float bv = b_dt[d];
#pragma unroll
        for (int bb = 0; bb < BT2; bb++) {
            float z = acc[bb] + bv;
            sdt[bb * DCH2 + tid] = (z > 20.f) ? z : log1pf(expf(z));
        }
    }
    __syncthreads();                        // sdt, sbc ready

    // ---- Phase 2: SSM readout
    const int dl = tid >> 2;                // 0..63
    const int q  = tid & 3;                 // n-quartet / result lane
    const int e0 = q & 1;
    const float4* h4  = reinterpret_cast<const float4*>(h);
    const float4* na4 = reinterpret_cast<const float4*>(g_negA);

#pragma unroll
    for (int p = 0; p < DCH2 / 64; p++) {
        const int dd = p * 64 + dl;
        const int dg = blockIdx.y * DCH2 + dd;
        float4 na  = na4[dg * (NS / 4) + q];
        float Dval = Dv[dg];

#pragma unroll
        for (int g = 0; g < BT2 / 4; g++) {
            // issue all independent loads first (MLP=4+)
            float4 hv[4];
#pragma unroll
            for (int j = 0; j < 4; j++)
                hv[j] = h4[((b0 + g * 4 + j) * DI + dg) * (NS / 4) + q];
            float dt0 = sdt[(g * 4 + 0) * DCH2 + dd];
            float dt1 = sdt[(g * 4 + 1) * DCH2 + dd];
            float dt2 = sdt[(g * 4 + 2) * DCH2 + dd];
            float dt3 = sdt[(g * 4 + 3) * DCH2 + dd];

            float s0, s1, s2, s3;
            {
                float4 Cq = *reinterpret_cast<const float4*>(sBC + (g*4+0) * 32 + NS + 4 * q);
                s0 = ex2(dt0 * na.x) * hv[0].x * Cq.x + ex2(dt0 * na.y) * hv[0].y * Cq.y
                   + ex2(dt0 * na.z) * hv[0].z * Cq.z + ex2(dt0 * na.w) * hv[0].w * Cq.w;
            }
            {
                float4 Cq = *reinterpret_cast<const float4*>(sBC + (g*4+1) * 32 + NS + 4 * q);
                s1 = ex2(dt1 * na.x) * hv[1].x * Cq.x + ex2(dt1 * na.y) * hv[1].y * Cq.y
                   + ex2(dt1 * na.z) * hv[1].z * Cq.z + ex2(dt1 * na.w) * hv[1].w * Cq.w;
            }
            {
                float4 Cq = *reinterpret_cast<const float4*>(sBC + (g*4+2) * 32 + NS + 4 * q);
                s2 = ex2(dt2 * na.x) * hv[2].x * Cq.x + ex2(dt2 * na.y) * hv[2].y * Cq.y
                   + ex2(dt2 * na.z) * hv[2].z * Cq.z + ex2(dt2 * na.w) * hv[2].w * Cq.w;
            }
            {
                float4 Cq = *reinterpret_cast<const float4*>(sBC + (g*4+3) * 32 + NS + 4 * q);
                s3 = ex2(dt3 * na.x) * hv[3].x * Cq.x + ex2(dt3 * na.y) * hv[3].y * Cq.y
                   + ex2(dt3 * na.z) * hv[3].z * Cq.z + ex2(dt3 * na.w) * hv[3].w * Cq.w;
            }

            // butterfly-transpose: lane q ends with full sum for bb = g*4+q
            float keepA = e0 ? s1 : s0;
            float keepB = e0 ? s3 : s2;
            float sendA = e0 ? s0 : s1;
            float sendB = e0 ? s2 : s3;
            keepA += __shfl_xor_sync(0xFFFFFFFF, sendA, 1);
            keepB += __shfl_xor_sync(0xFFFFFFFF, sendB, 1);
            float keep = (q & 2) ? keepB : keepA;
            float send = (q & 2) ? keepA : keepB;
            keep += __shfl_xor_sync(0xFFFFFFFF, send, 2);

            // per-lane dt / bc for its own batch (SELs, no dynamic reg indexing)
            float dtq = (q & 2) ? (e0 ? dt3 : dt2) : (e0 ? dt1 : dt0);
            const int bb = g * 4 + q;
            float bcq = sbc[bb];
            float xv  = x[(b0 + bb) * DI + dg];
            y[(b0 + bb) * DI + dg] = keep + xv * (dtq * bcq + Dval);
        }
    }
}

// ----------------------------------------------------------------
extern "C" void kernel_launch(void* const* d_in, const int* in_sizes, int n_in,
                              void* d_out, int out_size) {
    const float* x    = (const float*)d_in[0];
    const float* h    = (const float*)d_in[1];
    const float* Wd   = (const float*)d_in[2];
    const float* Wdt  = (const float*)d_in[3];
    const float* bdt  = (const float*)d_in[4];
    const float* Alog = (const float*)d_in[5];
    const float* WB   = (const float*)d_in[6];
    const float* WC   = (const float*)d_in[7];
    const float* D    = (const float*)d_in[8];
    float* y = (float*)d_out;

    k_prep  <<<(DI * NS + 255) / 256, 256>>>(Alog);
    k_gemm1 <<<dim3(BATCH / BT1, KS1), RX>>>(x, Wd, WB, WC);
    k_reduce<<<(BATCH * RX / 4 + 255) / 256, 256>>>();
    k_fused2<<<dim3(BATCH / BT2, DI / DCH2), DCH2>>>(x, h, Wdt, bdt, D, y);
}

// round 15
// speedup vs baseline: 1.2335x; 1.2335x over previous
#include <cuda_runtime.h>
#include <math.h>

#define BATCH 256
#define DI    5120
#define RNK   160
#define NS    16
#define RX    192            // 160 (delta) + 16 (B) + 16 (C)

#define KS1   40             // split-K factor for GEMM1
#define KCH   (DI / KS1)     // 128
#define BT1   8              // batch tile GEMM1
#define WCH   16             // w prefetch chunk GEMM1

#define BT2   4              // batch tile fused kernel
#define DCH2  256            // d's (= threads) per fused block
#define RCH   8              // Wdt prefetch chunk

#define LOG2E 1.4426950408889634f

// ---- scratch (no dynamic allocation allowed) ----
__device__ float g_part[KS1 * BATCH * RX];   // GEMM1 split-K partials
__device__ float g_xd[BATCH * RX];           // [xd | Bp | C]
__device__ float g_negA[DI * NS];            // [d][n]: -exp(A_log)*log2e

__device__ __forceinline__ float ex2(float v) {
    float r;
    asm("ex2.approx.ftz.f32 %0, %1;" : "=f"(r) : "f"(v));
    return r;
}

// ---------------------------------------------------------------- GEMM1 core
template <int WSTR>
__device__ __forceinline__ void gemm1_core(const float* __restrict__ w0,
                                           const float* __restrict__ xs,
                                           float* __restrict__ acc) {
    float wbuf[2][WCH];
    const float* wp = w0;
#pragma unroll
    for (int j = 0; j < WCH; j++) wbuf[0][j] = wp[j * WSTR];

#pragma unroll
    for (int c = 0; c < KCH / WCH; c++) {
        const int cur = c & 1;                 // compile-time
        if (c + 1 < KCH / WCH) {
            const float* wn = wp + WCH * WSTR;
#pragma unroll
            for (int j = 0; j < WCH; j++) wbuf[cur ^ 1][j] = wn[j * WSTR];
        }
#pragma unroll
        for (int j = 0; j < WCH; j++) {
            float w = wbuf[cur][j];
            const float4* xv4 = reinterpret_cast<const float4*>(xs + (c * WCH + j) * BT1);
#pragma unroll
            for (int q = 0; q < BT1 / 4; q++) {
                float4 xv = xv4[q];
                acc[4*q+0] += xv.x * w;
                acc[4*q+1] += xv.y * w;
                acc[4*q+2] += xv.z * w;
                acc[4*q+3] += xv.w * w;
            }
        }
        wp += WCH * WSTR;
    }
}

// ---------------------------------------------------------------- GEMM1 (+ negA prep folded in)
__global__ void __launch_bounds__(RX)
k_gemm1(const float* __restrict__ x,
        const float* __restrict__ Wd,
        const float* __restrict__ WB,
        const float* __restrict__ WC,
        const float* __restrict__ A_log) {
    __shared__ float xs[KCH * BT1];         // [kk][bb]  4 KB
    const int r  = threadIdx.x;             // 0..191
    const int b0 = blockIdx.x * BT1;
    const int k0 = blockIdx.y * KCH;

    for (int i = r; i < KCH * BT1; i += RX) {
        int bb = i / KCH, kk = i - bb * KCH;
        xs[kk * BT1 + bb] = x[(b0 + bb) * DI + k0 + kk];
    }

    // folded prep: first 81920 of 245760 global threads each handle one element
    {
        int g = (blockIdx.y * (BATCH / BT1) + blockIdx.x) * RX + r;
        if (g < DI * NS) g_negA[g] = -expf(A_log[g]) * LOG2E;
    }

    float acc[BT1];
#pragma unroll
    for (int i = 0; i < BT1; i++) acc[i] = 0.f;

    __syncthreads();

    if (r < 160) {
        gemm1_core<160>(Wd + r + k0 * 160, xs, acc);
    } else {
        const float* wb = (r < 176) ? (WB + (r - 160) + k0 * 16)
                                    : (WC + (r - 176) + k0 * 16);
        gemm1_core<16>(wb, xs, acc);
    }

    float* out = g_part + (blockIdx.y * BATCH + b0) * RX + r;
#pragma unroll
    for (int bb = 0; bb < BT1; bb++) out[bb * RX] = acc[bb];
}

// ---------------------------------------------------------------- reduce
__global__ void k_reduce() {
    int i = blockIdx.x * blockDim.x + threadIdx.x;    // float4 index
    if (i >= BATCH * RX / 4) return;
    const float4* p = reinterpret_cast<const float4*>(g_part) + i;
    float4 s = make_float4(0.f, 0.f, 0.f, 0.f);
#pragma unroll
    for (int ks = 0; ks < KS1; ks++) {
        float4 v = p[ks * (BATCH * RX / 4)];
        s.x += v.x; s.y += v.y; s.z += v.z; s.w += v.w;
    }
    reinterpret_cast<float4*>(g_xd)[i] = s;
}

// ---------------------------------------------------------------- fused GEMM2 + softplus + SSM
// Exact R12 structure (best measured) + minBlocksPerSM=5 to lift residency.
__global__ void __launch_bounds__(DCH2, 5)
k_fused2(const float* __restrict__ x,
         const float* __restrict__ h,
         const float* __restrict__ Wdt,
         const float* __restrict__ b_dt,
         const float* __restrict__ Dv,
         float* __restrict__ y) {
    __shared__ float xds[RNK * BT2];        // [r][bb]   2.5 KB
    __shared__ float sdt[BT2 * DCH2];       // [bb][d]   4 KB
    __shared__ float sBC[BT2 * 2 * NS];     // per batch: B[16] | C[16]
    __shared__ float sbc[BT2];              // dot(B,C) per batch
    const int tid = threadIdx.x;            // 0..255
    const int d   = blockIdx.x * DCH2 + tid;
    const int b0  = blockIdx.y * BT2;

    for (int i = tid; i < RNK * BT2; i += DCH2) {
        int bb = i / RNK, r = i - bb * RNK;
        xds[r * BT2 + bb] = g_xd[(b0 + bb) * RX + r];
    }
    if (tid < BT2 * 2 * NS) {
        int bb = tid >> 5, j = tid & 31;
        sBC[tid] = g_xd[(b0 + bb) * RX + 160 + j];
    }
    __syncthreads();

    if (tid < BT2) {
        float s = 0.f;
#pragma unroll
        for (int n = 0; n < NS; n++) s += sBC[tid * 32 + n] * sBC[tid * 32 + NS + n];
        sbc[tid] = s;
    }

    // ---- Phase 1: GEMM2 (register double-buffered W, fully unrolled)
    float acc[BT2];
#pragma unroll
    for (int i = 0; i < BT2; i++) acc[i] = 0.f;

    const float* wp = Wdt + d;
    float wbuf[2][RCH];
#pragma unroll
    for (int j = 0; j < RCH; j++) wbuf[0][j] = wp[j * DI];

#pragma unroll
    for (int c = 0; c < RNK / RCH; c++) {
        const int cur = c & 1;                 // compile-time
        if (c + 1 < RNK / RCH) {
            const float* wn = wp + RCH * DI;
#pragma unroll
            for (int j = 0; j < RCH; j++) wbuf[cur ^ 1][j] = wn[j * DI];
        }
        const int rbase = c * RCH;
#pragma unroll
        for (int j = 0; j < RCH; j++) {
            float w = wbuf[cur][j];
            float4 xv = *reinterpret_cast<const float4*>(xds + (rbase + j) * BT2);
            acc[0] += xv.x * w;  acc[1] += xv.y * w;
            acc[2] += xv.z * w;  acc[3] += xv.w * w;
        }
        wp += RCH * DI;
    }

    float bv = b_dt[d];
#pragma unroll
    for (int bb = 0; bb < BT2; bb++) {
        float z = acc[bb] + bv;
        sdt[bb * DCH2 + tid] = (z > 20.f) ? z : log1pf(expf(z));
    }
    __syncthreads();                        // sdt, sbc ready

    // ---- Phase 2: SSM readout, 4 lanes per d, batched loads (MLP>=4)
    const int dl = tid >> 2;                // 0..63
    const int q  = tid & 3;                 // n-quartet
    const float4* h4  = reinterpret_cast<const float4*>(h);
    const float4* na4 = reinterpret_cast<const float4*>(g_negA);

#pragma unroll
    for (int p = 0; p < DCH2 / 64; p++) {
        const int dd = p * 64 + dl;
        const int dg = blockIdx.x * DCH2 + dd;

        // issue all independent loads first
        float4 na = na4[dg * (NS / 4) + q];
        float4 hv[BT2];
#pragma unroll
        for (int bb = 0; bb < BT2; bb++)
            hv[bb] = h4[((b0 + bb) * DI + dg) * (NS / 4) + q];
        float dts[BT2];
#pragma unroll
        for (int bb = 0; bb < BT2; bb++) dts[bb] = sdt[bb * DCH2 + dd];
        float Dval = Dv[dg];

#pragma unroll
        for (int bb = 0; bb < BT2; bb++) {
            float4 Cq = *reinterpret_cast<const float4*>(sBC + bb * 32 + NS + 4 * q);
            float dtv = dts[bb];
            float s = ex2(dtv * na.x) * hv[bb].x * Cq.x
                    + ex2(dtv * na.y) * hv[bb].y * Cq.y
                    + ex2(dtv * na.z) * hv[bb].z * Cq.z
                    + ex2(dtv * na.w) * hv[bb].w * Cq.w;
            s += __shfl_xor_sync(0xFFFFFFFF, s, 1);
            s += __shfl_xor_sync(0xFFFFFFFF, s, 2);
            if (q == 0) {
                float xv = x[(b0 + bb) * DI + dg];
                y[(b0 + bb) * DI + dg] = s + xv * (dtv * sbc[bb] + Dval);
            }
        }
    }
}

// ----------------------------------------------------------------
extern "C" void kernel_launch(void* const* d_in, const int* in_sizes, int n_in,
                              void* d_out, int out_size) {
    const float* x    = (const float*)d_in[0];
    const float* h    = (const float*)d_in[1];
    const float* Wd   = (const float*)d_in[2];
    const float* Wdt  = (const float*)d_in[3];
    const float* bdt  = (const float*)d_in[4];
    const float* Alog = (const float*)d_in[5];
    const float* WB   = (const float*)d_in[6];
    const float* WC   = (const float*)d_in[7];
    const float* D    = (const float*)d_in[8];
    float* y = (float*)d_out;

    k_gemm1 <<<dim3(BATCH / BT1, KS1), RX>>>(x, Wd, WB, WC, Alog);
    k_reduce<<<(BATCH * RX / 4 + 255) / 256, 256>>>();
    k_fused2<<<dim3(DI / DCH2, BATCH / BT2), DCH2>>>(x, h, Wdt, bdt, D, y);
}

// round 16
// speedup vs baseline: 1.3087x; 1.0610x over previous
#include <cuda_runtime.h>
#include <math.h>

#define BATCH 256
#define DI    5120
#define RNK   160
#define NS    16
#define RX    192            // 160 (delta) + 16 (B) + 16 (C)

#define KS1   40             // split-K factor for GEMM1
#define KCH   (DI / KS1)     // 128
#define BT1   8              // batch tile GEMM1
#define WCH   16             // w prefetch chunk GEMM1

#define BT2   4              // batch tile fused kernel
#define DCH2  256            // d's (= threads) per fused block
#define RCH   8              // Wdt prefetch chunk

#define LOG2E 1.4426950408889634f

typedef unsigned long long u64;

// ---- scratch (no dynamic allocation allowed) ----
__device__ float g_part[KS1 * BATCH * RX];   // GEMM1 split-K partials
__device__ float g_xd[BATCH * RX];           // [xd | Bp | C]
__device__ float g_negA[DI * NS];            // [d][n]: -exp(A_log)*log2e

__device__ __forceinline__ float ex2(float v) {
    float r;
    asm("ex2.approx.ftz.f32 %0, %1;" : "=f"(r) : "f"(v));
    return r;
}
// packed fp32 pair FMA (FFMA2) — ptxas never auto-fuses; PTX-only
__device__ __forceinline__ u64 ffma2(u64 a, u64 b, u64 c) {
    u64 d;
    asm("fma.rn.f32x2 %0, %1, %2, %3;" : "=l"(d) : "l"(a), "l"(b), "l"(c));
    return d;
}
__device__ __forceinline__ u64 pack2(float w) {
    u64 r;
    asm("mov.b64 %0, {%1, %1};" : "=l"(r) : "f"(w));
    return r;
}
__device__ __forceinline__ void unpack2(u64 v, float& lo, float& hi) {
    asm("mov.b64 {%0, %1}, %2;" : "=f"(lo), "=f"(hi) : "l"(v));
}

// ---------------------------------------------------------------- GEMM1 core (packed)
template <int WSTR>
__device__ __forceinline__ void gemm1_core(const float* __restrict__ w0,
                                           const float* __restrict__ xs,
                                           u64* __restrict__ acc2) {
    float wbuf[2][WCH];
    const float* wp = w0;
#pragma unroll
    for (int j = 0; j < WCH; j++) wbuf[0][j] = wp[j * WSTR];

#pragma unroll
    for (int c = 0; c < KCH / WCH; c++) {
        const int cur = c & 1;                 // compile-time
        if (c + 1 < KCH / WCH) {
            const float* wn = wp + WCH * WSTR;
#pragma unroll
            for (int j = 0; j < WCH; j++) wbuf[cur ^ 1][j] = wn[j * WSTR];
        }
#pragma unroll
        for (int j = 0; j < WCH; j++) {
            u64 w2 = pack2(wbuf[cur][j]);
            const ulonglong2* xv2 = reinterpret_cast<const ulonglong2*>(
                xs + (c * WCH + j) * BT1);
            ulonglong2 xa = xv2[0];            // batches 0-3 (two f32x2)
            ulonglong2 xb = xv2[1];            // batches 4-7
            acc2[0] = ffma2(xa.x, w2, acc2[0]);
            acc2[1] = ffma2(xa.y, w2, acc2[1]);
            acc2[2] = ffma2(xb.x, w2, acc2[2]);
            acc2[3] = ffma2(xb.y, w2, acc2[3]);
        }
        wp += WCH * WSTR;
    }
}

// ---------------------------------------------------------------- GEMM1 (+ negA prep folded in)
__global__ void __launch_bounds__(RX)
k_gemm1(const float* __restrict__ x,
        const float* __restrict__ Wd,
        const float* __restrict__ WB,
        const float* __restrict__ WC,
        const float* __restrict__ A_log) {
    __shared__ float xs[KCH * BT1];         // [kk][bb]  4 KB
    const int r  = threadIdx.x;             // 0..191
    const int b0 = blockIdx.x * BT1;
    const int k0 = blockIdx.y * KCH;

    for (int i = r; i < KCH * BT1; i += RX) {
        int bb = i / KCH, kk = i - bb * KCH;
        xs[kk * BT1 + bb] = x[(b0 + bb) * DI + k0 + kk];
    }

    // folded prep: first 81920 of 245760 global threads each handle one element
    {
        int g = (blockIdx.y * (BATCH / BT1) + blockIdx.x) * RX + r;
        if (g < DI * NS) g_negA[g] = -expf(A_log[g]) * LOG2E;
    }

    u64 acc2[BT1 / 2];
#pragma unroll
    for (int i = 0; i < BT1 / 2; i++) acc2[i] = 0ull;

    __syncthreads();

    if (r < 160) {
        gemm1_core<160>(Wd + r + k0 * 160, xs, acc2);
    } else {
        const float* wb = (r < 176) ? (WB + (r - 160) + k0 * 16)
                                    : (WC + (r - 176) + k0 * 16);
        gemm1_core<16>(wb, xs, acc2);
    }

    float* out = g_part + (blockIdx.y * BATCH + b0) * RX + r;
#pragma unroll
    for (int i = 0; i < BT1 / 2; i++) {
        float lo, hi;
        unpack2(acc2[i], lo, hi);
        out[(2 * i) * RX]     = lo;
        out[(2 * i + 1) * RX] = hi;
    }
}

// ---------------------------------------------------------------- reduce
__global__ void k_reduce() {
    int i = blockIdx.x * blockDim.x + threadIdx.x;    // float4 index
    if (i >= BATCH * RX / 4) return;
    const float4* p = reinterpret_cast<const float4*>(g_part) + i;
    float4 s = make_float4(0.f, 0.f, 0.f, 0.f);
#pragma unroll
    for (int ks = 0; ks < KS1; ks++) {
        float4 v = p[ks * (BATCH * RX / 4)];
        s.x += v.x; s.y += v.y; s.z += v.z; s.w += v.w;
    }
    reinterpret_cast<float4*>(g_xd)[i] = s;
}

// ---------------------------------------------------------------- fused GEMM2 + softplus + SSM
// R15 structure + packed f32x2 phase-1 accumulation.
__global__ void __launch_bounds__(DCH2, 5)
k_fused2(const float* __restrict__ x,
         const float* __restrict__ h,
         const float* __restrict__ Wdt,
         const float* __restrict__ b_dt,
         const float* __restrict__ Dv,
         float* __restrict__ y) {
    __shared__ float xds[RNK * BT2];        // [r][bb]   2.5 KB
    __shared__ float sdt[BT2 * DCH2];       // [bb][d]   4 KB
    __shared__ float sBC[BT2 * 2 * NS];     // per batch: B[16] | C[16]
    __shared__ float sbc[BT2];              // dot(B,C) per batch
    const int tid = threadIdx.x;            // 0..255
    const int d   = blockIdx.x * DCH2 + tid;
    const int b0  = blockIdx.y * BT2;

    for (int i = tid; i < RNK * BT2; i += DCH2) {
        int bb = i / RNK, r = i - bb * RNK;
        xds[r * BT2 + bb] = g_xd[(b0 + bb) * RX + r];
    }
    if (tid < BT2 * 2 * NS) {
        int bb = tid >> 5, j = tid & 31;
        sBC[tid] = g_xd[(b0 + bb) * RX + 160 + j];
    }
    __syncthreads();

    if (tid < BT2) {
        float s = 0.f;
#pragma unroll
        for (int n = 0; n < NS; n++) s += sBC[tid * 32 + n] * sBC[tid * 32 + NS + n];
        sbc[tid] = s;
    }

    // ---- Phase 1: GEMM2 (register double-buffered W, packed f32x2 FMA)
    u64 acc2[BT2 / 2];
#pragma unroll
    for (int i = 0; i < BT2 / 2; i++) acc2[i] = 0ull;

    const float* wp = Wdt + d;
    float wbuf[2][RCH];
#pragma unroll
    for (int j = 0; j < RCH; j++) wbuf[0][j] = wp[j * DI];

#pragma unroll
    for (int c = 0; c < RNK / RCH; c++) {
        const int cur = c & 1;                 // compile-time
        if (c + 1 < RNK / RCH) {
            const float* wn = wp + RCH * DI;
#pragma unroll
            for (int j = 0; j < RCH; j++) wbuf[cur ^ 1][j] = wn[j * DI];
        }
        const int rbase = c * RCH;
#pragma unroll
        for (int j = 0; j < RCH; j++) {
            u64 w2 = pack2(wbuf[cur][j]);
            ulonglong2 xv = *reinterpret_cast<const ulonglong2*>(
                xds + (rbase + j) * BT2);
            acc2[0] = ffma2(xv.x, w2, acc2[0]);
            acc2[1] = ffma2(xv.y, w2, acc2[1]);
        }
        wp += RCH * DI;
    }

    {
        float bv = b_dt[d];
        float a0, a1, a2v, a3;
        unpack2(acc2[0], a0, a1);
        unpack2(acc2[1], a2v, a3);
        float z0 = a0 + bv, z1 = a1 + bv, z2 = a2v + bv, z3 = a3 + bv;
        sdt[0 * DCH2 + tid] = (z0 > 20.f) ? z0 : log1pf(expf(z0));
        sdt[1 * DCH2 + tid] = (z1 > 20.f) ? z1 : log1pf(expf(z1));
        sdt[2 * DCH2 + tid] = (z2 > 20.f) ? z2 : log1pf(expf(z2));
        sdt[3 * DCH2 + tid] = (z3 > 20.f) ? z3 : log1pf(expf(z3));
    }
    __syncthreads();                        // sdt, sbc ready

    // ---- Phase 2: SSM readout, 4 lanes per d, batched loads (MLP>=4)
    const int dl = tid >> 2;                // 0..63
    const int q  = tid & 3;                 // n-quartet
    const float4* h4  = reinterpret_cast<const float4*>(h);
    const float4* na4 = reinterpret_cast<const float4*>(g_negA);

#pragma unroll
    for (int p = 0; p < DCH2 / 64; p++) {
        const int dd = p * 64 + dl;
        const int dg = blockIdx.x * DCH2 + dd;

        // issue all independent loads first
        float4 na = na4[dg * (NS / 4) + q];
        float4 hv[BT2];
#pragma unroll
        for (int bb = 0; bb < BT2; bb++)
            hv[bb] = h4[((b0 + bb) * DI + dg) * (NS / 4) + q];
        float dts[BT2];
#pragma unroll
        for (int bb = 0; bb < BT2; bb++) dts[bb] = sdt[bb * DCH2 + dd];
        float Dval = Dv[dg];

#pragma unroll
        for (int bb = 0; bb < BT2; bb++) {
            float4 Cq = *reinterpret_cast<const float4*>(sBC + bb * 32 + NS + 4 * q);
            float dtv = dts[bb];
            float s = ex2(dtv * na.x) * hv[bb].x * Cq.x
                    + ex2(dtv * na.y) * hv[bb].y * Cq.y
                    + ex2(dtv * na.z) * hv[bb].z * Cq.z
                    + ex2(dtv * na.w) * hv[bb].w * Cq.w;
            s += __shfl_xor_sync(0xFFFFFFFF, s, 1);
            s += __shfl_xor_sync(0xFFFFFFFF, s, 2);
            if (q == 0) {
                float xv = x[(b0 + bb) * DI + dg];
                y[(b0 + bb) * DI + dg] = s + xv * (dtv * sbc[bb] + Dval);
            }
        }
    }
}

// ----------------------------------------------------------------
extern "C" void kernel_launch(void* const* d_in, const int* in_sizes, int n_in,
                              void* d_out, int out_size) {
    const float* x    = (const float*)d_in[0];
    const float* h    = (const float*)d_in[1];
    const float* Wd   = (const float*)d_in[2];
    const float* Wdt  = (const float*)d_in[3];
    const float* bdt  = (const float*)d_in[4];
    const float* Alog = (const float*)d_in[5];
    const float* WB   = (const float*)d_in[6];
    const float* WC   = (const float*)d_in[7];
    const float* D    = (const float*)d_in[8];
    float* y = (float*)d_out;

    k_gemm1 <<<dim3(BATCH / BT1, KS1), RX>>>(x, Wd, WB, WC, Alog);
    k_reduce<<<(BATCH * RX / 4 + 255) / 256, 256>>>();
    k_fused2<<<dim3(DI / DCH2, BATCH / BT2), DCH2>>>(x, h, Wdt, bdt, D, y);
}

// round 17
// speedup vs baseline: 1.3366x; 1.0212x over previous
#include <cuda_runtime.h>
#include <math.h>

#define BATCH 256
#define DI    5120
#define RNK   160
#define NS    16
#define RX    192            // 160 (delta) + 16 (B) + 16 (C)

#define KS1   40             // split-K factor for GEMM1
#define KCH   (DI / KS1)     // 128
#define BT1   8              // batch tile GEMM1
#define WCH   8              // w prefetch chunk GEMM1 (16 regs -> actually fits now)

#define BT2   4              // batch tile fused kernel
#define DCH2  256            // d's (= threads) per fused block
#define RCH   8              // Wdt prefetch chunk

#define LOG2E 1.4426950408889634f

typedef unsigned long long u64;

// ---- scratch (no dynamic allocation allowed) ----
__device__ float g_part[KS1 * BATCH * RX];   // GEMM1 split-K partials
__device__ float g_xd[BATCH * RX];           // [xd | Bp | C]
__device__ float g_negA[DI * NS];            // [d][n]: -exp(A_log)*log2e

__device__ __forceinline__ float ex2(float v) {
    float r;
    asm("ex2.approx.ftz.f32 %0, %1;" : "=f"(r) : "f"(v));
    return r;
}
// packed fp32 pair FMA (FFMA2) — ptxas never auto-fuses; PTX-only
__device__ __forceinline__ u64 ffma2(u64 a, u64 b, u64 c) {
    u64 d;
    asm("fma.rn.f32x2 %0, %1, %2, %3;" : "=l"(d) : "l"(a), "l"(b), "l"(c));
    return d;
}
__device__ __forceinline__ u64 pack2(float w) {
    u64 r;
    asm("mov.b64 %0, {%1, %1};" : "=l"(r) : "f"(w));
    return r;
}
__device__ __forceinline__ void unpack2(u64 v, float& lo, float& hi) {
    asm("mov.b64 {%0, %1}, %2;" : "=f"(lo), "=f"(hi) : "l"(v));
}

// ---------------------------------------------------------------- GEMM1 core (packed)
template <int WSTR>
__device__ __forceinline__ void gemm1_core(const float* __restrict__ w0,
                                           const float* __restrict__ xs,
                                           u64* __restrict__ acc2) {
    float wbuf[2][WCH];
    const float* wp = w0;
#pragma unroll
    for (int j = 0; j < WCH; j++) wbuf[0][j] = wp[j * WSTR];

#pragma unroll
    for (int c = 0; c < KCH / WCH; c++) {
        const int cur = c & 1;                 // compile-time
        if (c + 1 < KCH / WCH) {
            const float* wn = wp + WCH * WSTR;
#pragma unroll
            for (int j = 0; j < WCH; j++) wbuf[cur ^ 1][j] = wn[j * WSTR];
        }
#pragma unroll
        for (int j = 0; j < WCH; j++) {
            u64 w2 = pack2(wbuf[cur][j]);
            const ulonglong2* xv2 = reinterpret_cast<const ulonglong2*>(
                xs + (c * WCH + j) * BT1);
            ulonglong2 xa = xv2[0];            // batches 0-3 (two f32x2)
            ulonglong2 xb = xv2[1];            // batches 4-7
            acc2[0] = ffma2(xa.x, w2, acc2[0]);
            acc2[1] = ffma2(xa.y, w2, acc2[1]);
            acc2[2] = ffma2(xb.x, w2, acc2[2]);
            acc2[3] = ffma2(xb.y, w2, acc2[3]);
        }
        wp += WCH * WSTR;
    }
}

// ---------------------------------------------------------------- GEMM1 (+ negA prep folded in)
// minBlocksPerSM=6 -> ~56-reg budget: wbuf truly register-resident (no local spill).
__global__ void __launch_bounds__(RX, 6)
k_gemm1(const float* __restrict__ x,
        const float* __restrict__ Wd,
        const float* __restrict__ WB,
        const float* __restrict__ WC,
        const float* __restrict__ A_log) {
    __shared__ float xs[KCH * BT1];         // [kk][bb]  4 KB
    const int r  = threadIdx.x;             // 0..191
    const int b0 = blockIdx.x * BT1;
    const int k0 = blockIdx.y * KCH;

    for (int i = r; i < KCH * BT1; i += RX) {
        int bb = i / KCH, kk = i - bb * KCH;
        xs[kk * BT1 + bb] = x[(b0 + bb) * DI + k0 + kk];
    }

    // folded prep: first 81920 of 245760 global threads each handle one element
    {
        int g = (blockIdx.y * (BATCH / BT1) + blockIdx.x) * RX + r;
        if (g < DI * NS) g_negA[g] = -expf(A_log[g]) * LOG2E;
    }

    u64 acc2[BT1 / 2];
#pragma unroll
    for (int i = 0; i < BT1 / 2; i++) acc2[i] = 0ull;

    __syncthreads();

    if (r < 160) {
        gemm1_core<160>(Wd + r + k0 * 160, xs, acc2);
    } else {
        const float* wb = (r < 176) ? (WB + (r - 160) + k0 * 16)
                                    : (WC + (r - 176) + k0 * 16);
        gemm1_core<16>(wb, xs, acc2);
    }

    float* out = g_part + (blockIdx.y * BATCH + b0) * RX + r;
#pragma unroll
    for (int i = 0; i < BT1 / 2; i++) {
        float lo, hi;
        unpack2(acc2[i], lo, hi);
        out[(2 * i) * RX]     = lo;
        out[(2 * i + 1) * RX] = hi;
    }
}

// ---------------------------------------------------------------- reduce
__global__ void k_reduce() {
    int i = blockIdx.x * blockDim.x + threadIdx.x;    // float4 index
    if (i >= BATCH * RX / 4) return;
    const float4* p = reinterpret_cast<const float4*>(g_part) + i;
    float4 s = make_float4(0.f, 0.f, 0.f, 0.f);
#pragma unroll
    for (int ks = 0; ks < KS1; ks++) {
        float4 v = p[ks * (BATCH * RX / 4)];
        s.x += v.x; s.y += v.y; s.z += v.z; s.w += v.w;
    }
    reinterpret_cast<float4*>(g_xd)[i] = s;
}

// ---------------------------------------------------------------- fused GEMM2 + softplus + SSM
// R15 structure + packed f32x2 phase-1 accumulation.
__global__ void __launch_bounds__(DCH2, 5)
k_fused2(const float* __restrict__ x,
         const float* __restrict__ h,
         const float* __restrict__ Wdt,
         const float* __restrict__ b_dt,
         const float* __restrict__ Dv,
         float* __restrict__ y) {
    __shared__ float xds[RNK * BT2];        // [r][bb]   2.5 KB
    __shared__ float sdt[BT2 * DCH2];       // [bb][d]   4 KB
    __shared__ float sBC[BT2 * 2 * NS];     // per batch: B[16] | C[16]
    __shared__ float sbc[BT2];              // dot(B,C) per batch
    const int tid = threadIdx.x;            // 0..255
    const int d   = blockIdx.x * DCH2 + tid;
    const int b0  = blockIdx.y * BT2;

    for (int i = tid; i < RNK * BT2; i += DCH2) {
        int bb = i / RNK, r = i - bb * RNK;
        xds[r * BT2 + bb] = g_xd[(b0 + bb) * RX + r];
    }
    if (tid < BT2 * 2 * NS) {
        int bb = tid >> 5, j = tid & 31;
        sBC[tid] = g_xd[(b0 + bb) * RX + 160 + j];
    }
    __syncthreads();

    if (tid < BT2) {
        float s = 0.f;
#pragma unroll
        for (int n = 0; n < NS; n++) s += sBC[tid * 32 + n] * sBC[tid * 32 + NS + n];
        sbc[tid] = s;
    }

    // ---- Phase 1: GEMM2 (register double-buffered W, packed f32x2 FMA)
    u64 acc2[BT2 / 2];
#pragma unroll
    for (int i = 0; i < BT2 / 2; i++) acc2[i] = 0ull;

    const float* wp = Wdt + d;
    float wbuf[2][RCH];
#pragma unroll
    for (int j = 0; j < RCH; j++) wbuf[0][j] = wp[j * DI];

#pragma unroll
    for (int c = 0; c < RNK / RCH; c++) {
        const int cur = c & 1;                 // compile-time
        if (c + 1 < RNK / RCH) {
            const float* wn = wp + RCH * DI;
#pragma unroll
            for (int j = 0; j < RCH; j++) wbuf[cur ^ 1][j] = wn[j * DI];
        }
        const int rbase = c * RCH;
#pragma unroll
        for (int j = 0; j < RCH; j++) {
            u64 w2 = pack2(wbuf[cur][j]);
            ulonglong2 xv = *reinterpret_cast<const ulonglong2*>(
                xds + (rbase + j) * BT2);
            acc2[0] = ffma2(xv.x, w2, acc2[0]);
            acc2[1] = ffma2(xv.y, w2, acc2[1]);
        }
        wp += RCH * DI;
    }

    {
        float bv = b_dt[d];
        float a0, a1, a2v, a3;
        unpack2(acc2[0], a0, a1);
        unpack2(acc2[1], a2v, a3);
        float z0 = a0 + bv, z1 = a1 + bv, z2 = a2v + bv, z3 = a3 + bv;
        sdt[0 * DCH2 + tid] = (z0 > 20.f) ? z0 : log1pf(expf(z0));
        sdt[1 * DCH2 + tid] = (z1 > 20.f) ? z1 : log1pf(expf(z1));
        sdt[2 * DCH2 + tid] = (z2 > 20.f) ? z2 : log1pf(expf(z2));
        sdt[3 * DCH2 + tid] = (z3 > 20.f) ? z3 : log1pf(expf(z3));
    }
    __syncthreads();                        // sdt, sbc ready

    // ---- Phase 2: SSM readout, 4 lanes per d, batched loads (MLP>=4)
    const int dl = tid >> 2;                // 0..63
    const int q  = tid & 3;                 // n-quartet
    const float4* h4  = reinterpret_cast<const float4*>(h);
    const float4* na4 = reinterpret_cast<const float4*>(g_negA);

#pragma unroll
    for (int p = 0; p < DCH2 / 64; p++) {
        const int dd = p * 64 + dl;
        const int dg = blockIdx.x * DCH2 + dd;

        // issue all independent loads first
        float4 na = na4[dg * (NS / 4) + q];
        float4 hv[BT2];
#pragma unroll
        for (int bb = 0; bb < BT2; bb++)
            hv[bb] = h4[((b0 + bb) * DI + dg) * (NS / 4) + q];
        float dts[BT2];
#pragma unroll
        for (int bb = 0; bb < BT2; bb++) dts[bb] = sdt[bb * DCH2 + dd];
        float Dval = Dv[dg];

#pragma unroll
        for (int bb = 0; bb < BT2; bb++) {
            float4 Cq = *reinterpret_cast<const float4*>(sBC + bb * 32 + NS + 4 * q);
            float dtv = dts[bb];
            float s = ex2(dtv * na.x) * hv[bb].x * Cq.x
                    + ex2(dtv * na.y) * hv[bb].y * Cq.y
                    + ex2(dtv * na.z) * hv[bb].z * Cq.z
                    + ex2(dtv * na.w) * hv[bb].w * Cq.w;
            s += __shfl_xor_sync(0xFFFFFFFF, s, 1);
            s += __shfl_xor_sync(0xFFFFFFFF, s, 2);
            if (q == 0) {
                float xv = x[(b0 + bb) * DI + dg];
                y[(b0 + bb) * DI + dg] = s + xv * (dtv * sbc[bb] + Dval);
            }
        }
    }
}

// ----------------------------------------------------------------
extern "C" void kernel_launch(void* const* d_in, const int* in_sizes, int n_in,
                              void* d_out, int out_size) {
    const float* x    = (const float*)d_in[0];
    const float* h    = (const float*)d_in[1];
    const float* Wd   = (const float*)d_in[2];
    const float* Wdt  = (const float*)d_in[3];
    const float* bdt  = (const float*)d_in[4];
    const float* Alog = (const float*)d_in[5];
    const float* WB   = (const float*)d_in[6];
    const float* WC   = (const float*)d_in[7];
    const float* D    = (const float*)d_in[8];
    float* y = (float*)d_out;

    k_gemm1 <<<dim3(BATCH / BT1, KS1), RX>>>(x, Wd, WB, WC, Alog);
    k_reduce<<<(BATCH * RX / 4 + 255) / 256, 256>>>();
    k_fused2<<<dim3(DI / DCH2, BATCH / BT2), DCH2>>>(x, h, Wdt, bdt, D, y);
}